// round 16
// baseline (speedup 1.0000x reference)
#include <cuda_runtime.h>
#include <cuda_bf16.h>
#include <math.h>
#include <stdint.h>

#define NB   1024
#define NTOK 256
#define NV   200

// ---- HMMA tile config ----
#define MT    64       // batches per block
#define NT    64       // outputs per block
#define NKS   13
#define XSTR  216      // bf16 row stride in smem: 432B = 27*16
#define GKP   224      // global prepped row stride (bf16)

// dynamic smem offsets (bytes)
#define SM_XH  0
#define SM_XL  (SM_XH + MT * XSTR * 2)
#define SM_WH  (SM_XL + MT * XSTR * 2)
#define SM_WL  (SM_WH + NT * XSTR * 2)
#define SM_RED (SM_WL + NT * XSTR * 2)
#define SM_TOT (SM_RED + MT * 4 * 4)          // 111,616 B -> 2 blocks/SM

// ---------------- device scratch ----------------
__device__ float g_M[245];
__device__ float g_udp[3][NB][NV];
__device__ __align__(16) __nv_bfloat16 g_Xbf[2][3][NB][GKP];    // bnormed X hi/lo
__device__ __align__(16) __nv_bfloat16 g_Wbf[2][4][256][GKP];   // W^T hi/lo, padded

// ---------------- helpers ----------------
__device__ __forceinline__ float warp_sum(float v) {
#pragma unroll
    for (int o = 16; o; o >>= 1) v += __shfl_xor_sync(0xffffffffu, v, o);
    return v;
}
__device__ __forceinline__ float warp_max(float v) {
#pragma unroll
    for (int o = 16; o; o >>= 1) v = fmaxf(v, __shfl_xor_sync(0xffffffffu, v, o));
    return v;
}
__device__ __forceinline__ void mma16816(float* c, const uint32_t* a, const uint32_t* b) {
    asm volatile(
        "mma.sync.aligned.m16n8k16.row.col.f32.bf16.bf16.f32 "
        "{%0,%1,%2,%3}, {%4,%5,%6,%7}, {%8,%9}, {%0,%1,%2,%3};"
        : "+f"(c[0]), "+f"(c[1]), "+f"(c[2]), "+f"(c[3])
        : "r"(a[0]), "r"(a[1]), "r"(a[2]), "r"(a[3]), "r"(b[0]), "r"(b[1]));
}
__device__ __forceinline__ void ldmx4(uint32_t* r, uint32_t addr) {
    asm volatile("ldmatrix.sync.aligned.m8n8.x4.shared.b16 {%0,%1,%2,%3}, [%4];"
        : "=r"(r[0]), "=r"(r[1]), "=r"(r[2]), "=r"(r[3]) : "r"(addr));
}
__device__ __forceinline__ uint32_t smem_u32(const void* p) {
    uint32_t a;
    asm("{ .reg .u64 t; cvta.to.shared.u64 t, %1; cvt.u32.u64 %0, t; }" : "=r"(a) : "l"(p));
    return a;
}
__device__ __forceinline__ void cp16(uint32_t dst, const void* src) {
    asm volatile("cp.async.cg.shared.global [%0], [%1], 16;" :: "r"(dst), "l"(src));
}
__device__ __forceinline__ void cp_commit() {
    asm volatile("cp.async.commit_group;");
}
template <int N>
__device__ __forceinline__ void cp_wait() {
    asm volatile("cp.async.wait_group %0;" :: "n"(N));
}

// ---------------- kernel 0: M = Wq@Wk^T + W bf16 prep ----------------
__global__ void k_pre(const float* __restrict__ upWq, const float* __restrict__ upWk,
                      const float* __restrict__ dnWq, const float* __restrict__ dnWk,
                      const float* __restrict__ pvWq, const float* __restrict__ pvWk,
                      const float* __restrict__ tW1, const float* __restrict__ eW2) {
    int t = threadIdx.x;
    if (blockIdx.x == 0) {
        if (t >= 245) return;
        const float *Wq, *Wk; int j, f;
        if (t < 98)       { Wq = upWq; Wk = upWk; j = t / 14;        f = t % 14; }
        else if (t < 196) { Wq = dnWq; Wk = dnWk; j = (t - 98) / 14; f = (t - 98) % 14; }
        else              { Wq = pvWq; Wk = pvWk; j = (t - 196) / 7; f = (t - 196) % 7; }
        const float4* q4 = (const float4*)(Wq + j * NV);
        const float4* k4 = (const float4*)(Wk + f * NV);
        float s = 0.f;
#pragma unroll 5
        for (int v = 0; v < NV / 4; v++) {
            float4 qa = q4[v], ka = k4[v];
            s += qa.x * ka.x + qa.y * ka.y + qa.z * ka.z + qa.w * ka.w;
        }
        g_M[t] = s;
    } else {
        // W bf16 hi/lo prep: 4 units x 256 o x 224 k, split over 32 blocks
        int bi = blockIdx.x - 1;              // 0..31
        const int TOT = 4 * 256 * GKP;        // 229,376
        const int PER = TOT / 32;             // 7,168
        for (int i = bi * PER + t; i < (bi + 1) * PER; i += 256) {
            int unit = i / (256 * GKP);
            int r    = i - unit * 256 * GKP;
            int o    = r / GKP, k = r - o * GKP;
            const float* Wg = (unit < 3) ? tW1 + (size_t)unit * NV * NV : eW2;
            float wv = (o < NV && k < NV) ? Wg[(size_t)k * NV + o] : 0.f;
            __nv_bfloat16 h = __float2bfloat16(wv);
            g_Wbf[0][unit][o][k] = h;
            g_Wbf[1][unit][o][k] = __float2bfloat16(wv - __bfloat162float(h));
        }
    }
}

// ---------------- kernel 1: attention, block-per-batch ----------------
__global__ __launch_bounds__(256) void k_attn(
    const float* __restrict__ merged, const float* __restrict__ a,
    const float* __restrict__ upWv, const float* __restrict__ dnWv,
    const float* __restrict__ pvWv, float* __restrict__ out)
{
    __shared__ float feat[NTOK * 15];
    __shared__ float sM[245];
    __shared__ float sqk[35];
    __shared__ float wred[8][6];
    __shared__ float wpart[8][38];
    __shared__ float sred[38];

    int b = blockIdx.x, t = threadIdx.x;
    int wid = t >> 5, lane = t & 31;

    const float4* src4 = (const float4*)(merged + (size_t)b * NTOK * 15);
    float4* feat4 = (float4*)feat;
#pragma unroll
    for (int i = 0; i < 4; i++) {
        int idx = t + 256 * i;
        if (idx < 960) feat4[idx] = src4[idx];
    }
    if (b < 4) out[b * 256 + t] = 0.f;
    if (t < 245) sM[t] = g_M[t];
    float a_b = a[b];
    __syncthreads();

    float subj_id = feat[0], subj_loc = feat[2];
    if (t < 35) {
        float ego[7];
        ego[0] = 0.f; ego[1] = feat[1]; ego[2] = feat[2]; ego[3] = feat[3];
        ego[4] = feat[4]; ego[5] = feat[5]; ego[6] = a_b;
        float s = 0.f;
        if (t < 14) {
#pragma unroll
            for (int j = 0; j < 7; j++) s += ego[j] * sM[j * 14 + t];
        } else if (t < 28) {
            int f = t - 14;
#pragma unroll
            for (int j = 0; j < 7; j++) s += ego[j] * sM[98 + j * 14 + f];
        } else {
            int f = t - 28;
#pragma unroll
            for (int j = 0; j < 7; j++) s += ego[j] * sM[196 + j * 7 + f];
        }
        sqk[t] = s;
    }
    __syncthreads();

    float f[15];
#pragma unroll
    for (int q = 0; q < 15; q++) f[q] = feat[t * 15 + q];
    f[0] -= subj_id; f[7] -= subj_id;
    if (t == 0) f[6] = a_b;

    float s1 = 0.f, s2 = 0.f, s3 = 0.f;
#pragma unroll
    for (int q = 0; q < 14; q++) { s1 = fmaf(f[q], sqk[q], s1); s2 = fmaf(f[q], sqk[14 + q], s2); }
#pragma unroll
    for (int q = 0; q < 7; q++)  s3 = fmaf(f[q], sqk[28 + q], s3);

    const float scale = 0.07071067811865475f;
    bool fl1  = (f[14] == 1.0f);
    bool m_up = (f[2] < subj_loc) && fl1;
    bool m_dn = (f[2] > subj_loc) && fl1;
    bool m_pv = (f[14] == 0.0f);
    float su = m_up ? s1 * scale : -1e9f;
    float sd = m_dn ? s2 * scale : -1e9f;
    float sp = m_pv ? s3 * scale : -1e9f;

    float mu = warp_max(su), md = warp_max(sd), mp = warp_max(sp);
    float cu = warp_sum(m_up ? 1.f : 0.f);
    float cd = warp_sum(m_dn ? 1.f : 0.f);
    float cp = warp_sum(m_pv ? 1.f : 0.f);
    if (lane == 0) {
        wred[wid][0] = mu; wred[wid][1] = md; wred[wid][2] = mp;
        wred[wid][3] = cu; wred[wid][4] = cd; wred[wid][5] = cp;
    }
    __syncthreads();
    float BU = wred[0][0], BD = wred[0][1], BP = wred[0][2];
    float CU = wred[0][3], CD = wred[0][4], CP = wred[0][5];
#pragma unroll
    for (int w = 1; w < 8; w++) {
        BU = fmaxf(BU, wred[w][0]); BD = fmaxf(BD, wred[w][1]); BP = fmaxf(BP, wred[w][2]);
        CU += wred[w][3]; CD += wred[w][4]; CP += wred[w][5];
    }
    float eu = __expf(su - BU), ed = __expf(sd - BD), ep = __expf(sp - BP);

    float vals[38];
    vals[0] = eu; vals[1] = ed; vals[2] = ep;
#pragma unroll
    for (int q = 0; q < 14; q++) { vals[3 + q] = eu * f[q]; vals[17 + q] = ed * f[q]; }
#pragma unroll
    for (int q = 0; q < 7; q++)  vals[31 + q] = ep * f[q];
#pragma unroll
    for (int i = 0; i < 38; i++) {
        float v = warp_sum(vals[i]);
        if (lane == 0) wpart[wid][i] = v;
    }
    __syncthreads();
    if (t < 38) {
        float s = 0.f;
#pragma unroll
        for (int w = 0; w < 8; w++) s += wpart[w][t];
        sred[t] = s;
    }
    __syncthreads();

    if (t < NV) {
        float iSu = (CU > 0.5f) ? 1.f / sred[0] : 0.f;
        float iSd = (CD > 0.5f) ? 1.f / sred[1] : 0.f;
        float iSp = (CP > 0.5f) ? 1.f / sred[2] : 0.f;
        float ou = 0.f, od = 0.f, op = 0.f;
#pragma unroll
        for (int q = 0; q < 14; q++) {
            ou = fmaf(sred[3 + q],  __ldg(&upWv[q * NV + t]), ou);
            od = fmaf(sred[17 + q], __ldg(&dnWv[q * NV + t]), od);
        }
#pragma unroll
        for (int q = 0; q < 7; q++)
            op = fmaf(sred[31 + q], __ldg(&pvWv[q * NV + t]), op);
        g_udp[0][b][t] = ou * iSu;
        g_udp[1][b][t] = od * iSd;
        g_udp[2][b][t] = op * iSp;
    }
}

// ---------------- kernel 2: bnorm stats + bf16 X prep ----------------
__global__ void k_stats(const float* __restrict__ gamma, const float* __restrict__ beta) {
    int u  = blockIdx.y;
    int vx = threadIdx.x;
    int by = threadIdx.y;
    int v  = blockIdx.x * 32 + vx;        // 0..223 (7 stripes)
    float s = 0.f, s2 = 0.f;
    if (v < NV) {
#pragma unroll 4
        for (int j = 0; j < 32; j++) {
            float x = g_udp[u][by + 32 * j][v];
            s += x;
            s2 = fmaf(x, x, s2);
        }
    }
    __shared__ float ss[32][33], ss2[32][33];
    __shared__ float smean[32], srstd[32];
    ss[by][vx]  = s;
    ss2[by][vx] = s2;
    __syncthreads();
#pragma unroll
    for (int off = 16; off; off >>= 1) {
        if (by < off) {
            ss[by][vx]  += ss[by + off][vx];
            ss2[by][vx] += ss2[by + off][vx];
        }
        __syncthreads();
    }
    if (by == 0) {
        float mean = ss[0][vx] * (1.f / NB);
        float var  = ss2[0][vx] * (1.f / NB) - mean * mean;
        smean[vx] = mean;
        srstd[vx] = rsqrtf(var + 1e-5f);
    }
    __syncthreads();

    float gm = 0.f, bt = 0.f, mn = 0.f, rs = 0.f;
    if (v < NV) { gm = gamma[v]; bt = beta[v]; mn = smean[vx]; rs = srstd[vx]; }
#pragma unroll 4
    for (int j = 0; j < 32; j++) {
        int b = by + 32 * j;
        float xn = 0.f;
        if (v < NV) xn = gm * (g_udp[u][b][v] - mn) * rs + bt;
        __nv_bfloat16 hh = __float2bfloat16(xn);
        g_Xbf[0][u][b][v] = hh;
        g_Xbf[1][u][b][v] = __float2bfloat16(xn - __bfloat162float(hh));
    }
}

// ---------------- kernel 3: HMMA bf16 split GEMM, cp.async staged ----------------
// Block = 64 batches x 64 outputs x full K. grid (16, 4, 4), 2 blocks/SM.
// Staging: pure cp.async 16B copies of pre-converted bf16 (X, W); unit 3 X computed in parallel.
__global__ __launch_bounds__(256) void k_mlp(const float* __restrict__ merged,
                                             const float* __restrict__ a,
                                             const float* __restrict__ tb1,
                                             const float* __restrict__ tW2,
                                             const float* __restrict__ tb2,
                                             const float* __restrict__ eW1,
                                             const float* __restrict__ eb1,
                                             const float* __restrict__ eb2,
                                             const float* __restrict__ eW3,
                                             const float* __restrict__ eb3,
                                             float* __restrict__ out) {
    extern __shared__ char smem[];
    __nv_bfloat16* Xh = (__nv_bfloat16*)(smem + SM_XH);
    __nv_bfloat16* Xl = (__nv_bfloat16*)(smem + SM_XL);
    __nv_bfloat16* Wh = (__nv_bfloat16*)(smem + SM_WH);
    __nv_bfloat16* Wl = (__nv_bfloat16*)(smem + SM_WL);
    float*        red = (float*)(smem + SM_RED);          // [64][4]

    int t     = threadIdx.x;
    int wid   = t >> 5, lane = t & 31;
    int g     = lane >> 2;
    int la    = lane & 3;
    int wm    = wid >> 2;             // 0..1
    int wn    = wid & 3;              // 0..3
    int b0    = blockIdx.x * MT;
    int oBase = blockIdx.y * NT;
    int unit  = blockIdx.z;

    // ---- stage W via cp.async (26 x 16B per row) ----
    {
        uint32_t whb = smem_u32(Wh), wlb = smem_u32(Wl);
        const char* gwh = (const char*)&g_Wbf[0][unit][oBase][0];
        const char* gwl = (const char*)&g_Wbf[1][unit][oBase][0];
        for (int i = t; i < NT * 26; i += 256) {
            int r = i / 26, c = (i - r * 26) * 16;
            cp16(whb + r * (XSTR * 2) + c, gwh + r * (GKP * 2) + c);
            cp16(wlb + r * (XSTR * 2) + c, gwl + r * (GKP * 2) + c);
        }
    }
    // ---- stage X ----
    if (unit < 3) {
        uint32_t xhb = smem_u32(Xh), xlb = smem_u32(Xl);
        const char* gxh = (const char*)&g_Xbf[0][unit][b0][0];
        const char* gxl = (const char*)&g_Xbf[1][unit][b0][0];
        for (int i = t; i < MT * 26; i += 256) {
            int r = i / 26, c = (i - r * 26) * 16;
            cp16(xhb + r * (XSTR * 2) + c, gxh + r * (GKP * 2) + c);
            cp16(xlb + r * (XSTR * 2) + c, gxl + r * (GKP * 2) + c);
        }
    } else {
        // ego net X: h = relu(ego @ eW1 + eb1), computed in parallel (batch x k-quarter)
        int bb = t & 63;
        int kq = t >> 6;              // 0..3
        const float* mr = merged + (size_t)(b0 + bb) * NTOK * 15;
        float m3 = mr[3], m4 = mr[4], m5 = mr[5], ab = a[b0 + bb];
        for (int k = kq * 54; k < kq * 54 + 54; k++) {
            float h = 0.f;
            if (k < NV) {
                h = fmaxf(m3 * eW1[k] + m4 * eW1[NV + k] + m5 * eW1[2 * NV + k]
                          + ab * eW1[3 * NV + k] + eb1[k], 0.f);
            }
            __nv_bfloat16 hh = __float2bfloat16(h);
            Xh[bb * XSTR + k] = hh;
            Xl[bb * XSTR + k] = __float2bfloat16(h - __bfloat162float(hh));
        }
    }
    cp_commit();
    cp_wait<0>();
    __syncthreads();

    // ---- ldmatrix lane addresses ----
    int lrow  = (lane & 15);
    int khalf = (lane >> 4) & 1;
    uint32_t aXh0 = smem_u32(&Xh[(wm * 32 + lrow) * XSTR + khalf * 8]);
    uint32_t aXh1 = smem_u32(&Xh[(wm * 32 + 16 + lrow) * XSTR + khalf * 8]);
    uint32_t aXl0 = smem_u32(&Xl[(wm * 32 + lrow) * XSTR + khalf * 8]);
    uint32_t aXl1 = smem_u32(&Xl[(wm * 32 + 16 + lrow) * XSTR + khalf * 8]);
    uint32_t aWh  = smem_u32(&Wh[(wn * 16 + lrow) * XSTR + khalf * 8]);
    uint32_t aWl  = smem_u32(&Wl[(wn * 16 + lrow) * XSTR + khalf * 8]);

    // ---- HMMA main loop ----
    float chh[2][2][4], ccr[2][2][4];
#pragma unroll
    for (int mi = 0; mi < 2; mi++)
#pragma unroll
        for (int ni = 0; ni < 2; ni++)
#pragma unroll
            for (int j = 0; j < 4; j++) { chh[mi][ni][j] = 0.f; ccr[mi][ni][j] = 0.f; }

#pragma unroll
    for (int s = 0; s < NKS; s++) {
        uint32_t koff = (uint32_t)s * 32;
        uint32_t ah[2][4], al[2][4], wh[4], wl[4];
        ldmx4(ah[0], aXh0 + koff);
        ldmx4(ah[1], aXh1 + koff);
        ldmx4(al[0], aXl0 + koff);
        ldmx4(al[1], aXl1 + koff);
        ldmx4(wh, aWh + koff);
        ldmx4(wl, aWl + koff);
        uint32_t bh0[2] = {wh[0], wh[2]}, bh1[2] = {wh[1], wh[3]};
        uint32_t bl0[2] = {wl[0], wl[2]}, bl1[2] = {wl[1], wl[3]};
        mma16816(chh[0][0], ah[0], bh0); mma16816(chh[0][1], ah[0], bh1);
        mma16816(chh[1][0], ah[1], bh0); mma16816(chh[1][1], ah[1], bh1);
        mma16816(ccr[0][0], ah[0], bl0); mma16816(ccr[0][1], ah[0], bl1);
        mma16816(ccr[1][0], ah[1], bl0); mma16816(ccr[1][1], ah[1], bl1);
        mma16816(ccr[0][0], al[0], bh0); mma16816(ccr[0][1], al[0], bh1);
        mma16816(ccr[1][0], al[1], bh0); mma16816(ccr[1][1], al[1], bh1);
    }

    // ---- epilogue: bias + act + *W2, quad reduce, smem, atomicAdd ----
    const float* b1 = (unit < 3) ? tb1 + unit * NV : eb2;
    const float* w2 = (unit < 3) ? tW2 + unit * NV : eW3;

    float srow[2][2];
#pragma unroll
    for (int mi = 0; mi < 2; mi++) {
        srow[mi][0] = 0.f; srow[mi][1] = 0.f;
#pragma unroll
        for (int ni = 0; ni < 2; ni++) {
#pragma unroll
            for (int j = 0; j < 2; j++) {
                int oo = oBase + wn * 16 + ni * 8 + la * 2 + j;
                if (oo < NV) {
                    float bias = b1[oo], wv = w2[oo];
                    float v0 = chh[mi][ni][j]     + ccr[mi][ni][j]     + bias;
                    float v1 = chh[mi][ni][2 + j] + ccr[mi][ni][2 + j] + bias;
                    if (unit < 3) {
                        v0 = v0 > 0.f ? v0 : expm1f(v0);
                        v1 = v1 > 0.f ? v1 : expm1f(v1);
                    } else {
                        v0 = fmaxf(v0, 0.f);
                        v1 = fmaxf(v1, 0.f);
                    }
                    srow[mi][0] = fmaf(v0, wv, srow[mi][0]);
                    srow[mi][1] = fmaf(v1, wv, srow[mi][1]);
                }
            }
        }
#pragma unroll
        for (int off = 1; off <= 2; off <<= 1) {
            srow[mi][0] += __shfl_xor_sync(0xffffffffu, srow[mi][0], off);
            srow[mi][1] += __shfl_xor_sync(0xffffffffu, srow[mi][1], off);
        }
    }
    if (la == 0) {
#pragma unroll
        for (int mi = 0; mi < 2; mi++) {
            int r0 = wm * 32 + mi * 16 + g;
            red[r0 * 4 + wn]       = srow[mi][0];
            red[(r0 + 8) * 4 + wn] = srow[mi][1];
        }
    }
    __syncthreads();
    if (t < MT) {
        float s = red[t * 4 + 0] + red[t * 4 + 1] + red[t * 4 + 2] + red[t * 4 + 3];
        if (blockIdx.y == 0) s += (unit < 3) ? tb2[unit] : eb3[0];
        atomicAdd(&out[b0 + t], s);
    }
}

// ---------------- launch ----------------
extern "C" void kernel_launch(void* const* d_in, const int* in_sizes, int n_in,
                              void* d_out, int out_size) {
    (void)in_sizes; (void)n_in; (void)out_size;
    const float* merged = (const float*)d_in[0];
    const float* a      = (const float*)d_in[1];
    const float* upWq   = (const float*)d_in[2];
    const float* upWk   = (const float*)d_in[3];
    const float* upWv   = (const float*)d_in[4];
    const float* dnWq   = (const float*)d_in[5];
    const float* dnWk   = (const float*)d_in[6];
    const float* dnWv   = (const float*)d_in[7];
    const float* pvWq   = (const float*)d_in[8];
    const float* pvWk   = (const float*)d_in[9];
    const float* pvWv   = (const float*)d_in[10];
    const float* tW1    = (const float*)d_in[11];
    const float* tb1    = (const float*)d_in[12];
    const float* tW2    = (const float*)d_in[13];
    const float* tb2    = (const float*)d_in[14];
    const float* eW1    = (const float*)d_in[15];
    const float* eb1    = (const float*)d_in[16];
    const float* eW2    = (const float*)d_in[17];
    const float* eb2    = (const float*)d_in[18];
    const float* eW3    = (const float*)d_in[19];
    const float* eb3    = (const float*)d_in[20];
    const float* gamma  = (const float*)d_in[21];
    const float* beta   = (const float*)d_in[22];
    float* out = (float*)d_out;

    static bool attr_set = false;
    if (!attr_set) {
        cudaFuncSetAttribute(k_mlp, cudaFuncAttributeMaxDynamicSharedMemorySize, SM_TOT);
        attr_set = true;
    }

    k_pre<<<33, 256>>>(upWq, upWk, dnWq, dnWk, pvWq, pvWk, tW1, eW2);
    k_attn<<<NB, 256>>>(merged, a, upWv, dnWv, pvWv, out);
    k_stats<<<dim3(7, 3), dim3(32, 32)>>>(gamma, beta);
    k_mlp<<<dim3(NB / MT, 4, 4), 256, SM_TOT>>>(merged, a, tb1, tW2, tb2,
                                                eW1, eb1, eb2, eW3, eb3, out);
}